// round 4
// baseline (speedup 1.0000x reference)
#include <cuda_runtime.h>

#define CN    64
#define HH    256
#define HWSZ  65536
#define NCLS  6
#define NWIN  1024

typedef unsigned long long u64;

__device__ __forceinline__ u64 pk2(float lo, float hi) {
    u64 r; asm("mov.b64 %0, {%1, %2};" : "=l"(r) : "f"(lo), "f"(hi)); return r;
}
__device__ __forceinline__ u64 bc2(float v) { return pk2(v, v); }
__device__ __forceinline__ void fma2(u64& a, u64 x, u64 y) {
    asm("fma.rn.f32x2 %0, %1, %2, %0;" : "+l"(a) : "l"(x), "l"(y));
}
__device__ __forceinline__ float2 upk(u64 v) {
    float2 r; asm("mov.b64 {%0, %1}, %2;" : "=f"(r.x), "=f"(r.y) : "l"(v)); return r;
}

// ---------------- scratch (device globals; no allocations allowed) ----------
__device__ float g_mask[NCLS * NWIN * 64];
__device__ float g_good[NCLS * NWIN * 64];
__device__ float g_qk[(size_t)NCLS * NWIN * 8192];    // per-window q (4096) + k (4096)
__device__ float g_out1[(size_t)NCLS * CN * HWSZ];    // x + class_attn
__device__ float g_x112[(size_t)NCLS * CN * HWSZ];
__device__ float g_x223[(size_t)NCLS * CN * HWSZ];

// ---------------------------------------------------------------------------
// K1: qk conv (packed f32x2) + mask; stores q/k for reuse by k_attn.
//   q global layout: [oc][px]  (oc*64+px)
//   k global layout: [h][px][d] (h*1024 + px*16 + d)
// ---------------------------------------------------------------------------
__global__ __launch_bounds__(256)
void k_mask(const float* __restrict__ x, const float* __restrict__ qkw,
            const float* __restrict__ qks, const float* __restrict__ qkb,
            const float* __restrict__ relb) {
    int cls = blockIdx.y, win = blockIdx.x;
    int wy = win >> 5, wx = win & 31;
    extern __shared__ float sm[];
    float* xw   = sm;            // 4096
    float* wsm  = xw + 4096;     // 128*65 = 8320
    float* qk   = wsm + 8320;    // 128*65 = 8320
    float* kl   = qk + 8320;     // 4096  (k in [h][px][d])
    float* qsum = kl + 4096;     // 64
    float* rsm  = qsum + 64;     // 900
    int tid = threadIdx.x;
    const float* xb = x + ((size_t)cls * CN) * HWSZ;

    for (int id = tid; id < 512; id += 256) {
        int ch = id >> 3, i = id & 7;
        const float* p = xb + (size_t)ch * HWSZ + (wy * 8 + i) * HH + wx * 8;
        float4 a = *(const float4*)p;
        float4 b = *(const float4*)(p + 4);
        float* d = xw + ch * 64 + i * 8;
        d[0]=a.x; d[1]=a.y; d[2]=a.z; d[3]=a.w;
        d[4]=b.x; d[5]=b.y; d[6]=b.z; d[7]=b.w;
    }
    const float* wb = qkw + (size_t)cls * 8192;
    for (int id = tid; id < 8192; id += 256)
        wsm[(id >> 6) * 65 + (id & 63)] = wb[id];
    const float* rb = relb + cls * 900;
    for (int id = tid; id < 900; id += 256) rsm[id] = rb[id];
    __syncthreads();

    // qk 1x1 conv: thread = (oc pair, 16-px group); packed pairs.
    const float* sS = qks + cls * 128;
    const float* sB = qkb + cls * 128;
    {
        int ocp = tid >> 2;          // 0..63 -> oc {2*ocp, 2*ocp+1}
        int px0 = (tid & 3) * 16;
        u64 acc[2][8];
        #pragma unroll
        for (int r = 0; r < 2; r++)
            #pragma unroll
            for (int j = 0; j < 8; j++) acc[r][j] = 0ull;
        const float* w0r = wsm + (2 * ocp) * 65;
        const float* w1r = wsm + (2 * ocp + 1) * 65;
        #pragma unroll 4
        for (int c = 0; c < 64; c++) {
            u64 wa = bc2(w0r[c]);
            u64 wb2 = bc2(w1r[c]);
            const u64* xp = (const u64*)(xw + c * 64 + px0);
            #pragma unroll
            for (int j = 0; j < 8; j++) {
                u64 x2 = xp[j];
                fma2(acc[0][j], wa, x2);
                fma2(acc[1][j], wb2, x2);
            }
        }
        #pragma unroll
        for (int r = 0; r < 2; r++) {
            int oc = 2 * ocp + r;
            float s = sS[oc], b = sB[oc];
            #pragma unroll
            for (int j = 0; j < 8; j++) {
                float2 v = upk(acc[r][j]);
                qk[oc * 65 + px0 + 2 * j]     = fmaxf(v.x * s + b, 0.f);
                qk[oc * 65 + px0 + 2 * j + 1] = fmaxf(v.y * s + b, 0.f);
            }
        }
    }
    __syncthreads();

    // k-layout transform + q global store; qsum in parallel
    float* gbase = g_qk + (size_t)(cls * NWIN + win) * 8192;
    for (int id = tid; id < 4096; id += 256) {
        int h = id >> 10, rem = id & 1023, px = rem >> 4, d = rem & 15;
        kl[id] = qk[(64 + h * 16 + d) * 65 + px];
    }
    for (int id = tid; id < 4096; id += 256)
        gbase[id] = qk[(id >> 6) * 65 + (id & 63)];
    if (tid < 64) {
        float s = 0.f;
        const float* r = qk + tid * 65;
        #pragma unroll 16
        for (int p = 0; p < 64; p++) s += r[p];
        qsum[tid] = s;
    }
    __syncthreads();

    {
        float4* gk4 = (float4*)(gbase + 4096);
        const float4* kl4 = (const float4*)kl;
        for (int id = tid; id < 1024; id += 256) gk4[id] = kl4[id];
    }

    if (tid < 64) {
        int kp = tid, ik = kp >> 3, jk = kp & 7;
        float dot = 0.f;
        #pragma unroll 16
        for (int ch = 0; ch < 64; ch++) dot += qsum[ch] * qk[(64 + ch) * 65 + kp];
        float rbv = 0.f;
        for (int q = 0; q < 64; q++) {
            int ridx = ((q >> 3) - ik + 7) * 15 + ((q & 7) - jk + 7);
            const float* r4 = rsm + ridx * 4;
            rbv += r4[0] + r4[1] + r4[2] + r4[3];
        }
        g_mask[(cls * NWIN + win) * 64 + kp] = dot * (0.25f / 256.f) + rbv * (1.f / 256.f);
    }
}

// ---------------------------------------------------------------------------
// K2: good = (mask == max over classes) ? 1 : -1
// ---------------------------------------------------------------------------
__global__ void k_good() {
    int i = blockIdx.x * 256 + threadIdx.x;
    float m[NCLS], mx = -1e30f;
    #pragma unroll
    for (int c = 0; c < NCLS; c++) {
        m[c] = g_mask[c * NWIN * 64 + i];
        mx = fmaxf(mx, m[c]);
    }
    #pragma unroll
    for (int c = 0; c < NCLS; c++)
        g_good[c * NWIN * 64 + i] = (m[c] == mx) ? 1.f : -1.f;
}

// ---------------------------------------------------------------------------
// K3: attention (loads q/k from g_qk), v conv, softmax, mask, attn@v,
//     residual + un-window. Packed f32x2 throughout.
// ---------------------------------------------------------------------------
__global__ __launch_bounds__(256)
void k_attn(const float* __restrict__ x, const float* __restrict__ relb,
            const float* __restrict__ wvw, const float* __restrict__ wvs,
            const float* __restrict__ wvb) {
    int cls = blockIdx.y, win = blockIdx.x;
    int wy = win >> 5, wx = win & 31;
    extern __shared__ float sm[];
    float* xw  = sm;             // 4096
    float* qsm = xw + 4096;      // 4160 (64*65)
    float* ksm = qsm + 4160;     // 4096 [h][px][d]
    float* vsm = ksm + 4096;     // 4096 [h][px][d]
    float* wsm = vsm + 4096;     // 4160 (64*65)
    float* rsm = wsm + 4160;     // 900
    float* gsm = rsm + 900;      // 64
    float* osm = gsm + 64;       // 4096
    int tid = threadIdx.x;
    const float* xb = x + ((size_t)cls * CN) * HWSZ;

    for (int id = tid; id < 512; id += 256) {
        int ch = id >> 3, i = id & 7;
        const float* p = xb + (size_t)ch * HWSZ + (wy * 8 + i) * HH + wx * 8;
        float4 a = *(const float4*)p;
        float4 b = *(const float4*)(p + 4);
        float* d = xw + ch * 64 + i * 8;
        d[0]=a.x; d[1]=a.y; d[2]=a.z; d[3]=a.w;
        d[4]=b.x; d[5]=b.y; d[6]=b.z; d[7]=b.w;
    }
    const float* gbase = g_qk + (size_t)(cls * NWIN + win) * 8192;
    for (int id = tid; id < 4096; id += 256)
        qsm[(id >> 6) * 65 + (id & 63)] = gbase[id];
    {
        const float4* gk4 = (const float4*)(gbase + 4096);
        float4* k4 = (float4*)ksm;
        for (int id = tid; id < 1024; id += 256) k4[id] = gk4[id];
    }
    const float* wvwb = wvw + (size_t)cls * 4096;
    for (int id = tid; id < 4096; id += 256)
        wsm[(id >> 6) * 65 + (id & 63)] = wvwb[id];
    const float* rb = relb + cls * 900;
    for (int id = tid; id < 900; id += 256) rsm[id] = rb[id];
    if (tid < 64) gsm[tid] = g_good[(cls * NWIN + win) * 64 + tid];
    __syncthreads();

    // v conv: thread = (oc pair, 8-px group), packed
    {
        int ocp = tid >> 3;           // 0..31 -> oc {2*ocp, 2*ocp+1}
        int px0 = (tid & 7) * 8;
        u64 acc[2][4];
        #pragma unroll
        for (int r = 0; r < 2; r++)
            #pragma unroll
            for (int j = 0; j < 4; j++) acc[r][j] = 0ull;
        const float* w0r = wsm + (2 * ocp) * 65;
        const float* w1r = wsm + (2 * ocp + 1) * 65;
        #pragma unroll 4
        for (int c = 0; c < 64; c++) {
            u64 wa = bc2(w0r[c]);
            u64 wb2 = bc2(w1r[c]);
            const u64* xp = (const u64*)(xw + c * 64 + px0);
            #pragma unroll
            for (int j = 0; j < 4; j++) {
                u64 x2 = xp[j];
                fma2(acc[0][j], wa, x2);
                fma2(acc[1][j], wb2, x2);
            }
        }
        const float* vS = wvs + cls * 64;
        const float* vB = wvb + cls * 64;
        #pragma unroll
        for (int r = 0; r < 2; r++) {
            int oc = 2 * ocp + r;
            int h = oc >> 4, d = oc & 15;
            float s = vS[oc], b = vB[oc];
            #pragma unroll
            for (int j = 0; j < 4; j++) {
                float2 v = upk(acc[r][j]);
                vsm[h * 1024 + (px0 + 2 * j) * 16 + d]     = fmaxf(v.x * s + b, 0.f);
                vsm[h * 1024 + (px0 + 2 * j + 1) * 16 + d] = fmaxf(v.y * s + b, 0.f);
            }
        }
    }
    __syncthreads();

    // attention: thread = (head, query-pos)
    int h = tid >> 6, qp = tid & 63;
    int iq = qp >> 3, jq = qp & 7;
    u64 q2[8];
    #pragma unroll
    for (int j = 0; j < 8; j++)
        q2[j] = pk2(qsm[(h * 16 + 2 * j) * 65 + qp], qsm[(h * 16 + 2 * j + 1) * 65 + qp]);

    float a[64];
    const u64* kb2 = (const u64*)(ksm + h * 1024);
    #pragma unroll
    for (int kp = 0; kp < 64; kp++) {
        const u64* kr = kb2 + kp * 8;
        u64 dacc = 0ull;
        #pragma unroll
        for (int j = 0; j < 8; j++) fma2(dacc, q2[j], kr[j]);
        float2 dv = upk(dacc);
        int ridx = (iq - (kp >> 3) + 7) * 15 + (jq - (kp & 7) + 7);
        a[kp] = (dv.x + dv.y) * 0.25f + rsm[ridx * 4 + h];
    }
    float mx = -1e30f;
    #pragma unroll
    for (int kp = 0; kp < 64; kp++) mx = fmaxf(mx, a[kp]);
    float ssum = 0.f;
    #pragma unroll
    for (int kp = 0; kp < 64; kp++) { a[kp] = __expf(a[kp] - mx); ssum += a[kp]; }
    float gq = gsm[qp] / ssum;

    u64 o2[8];
    #pragma unroll
    for (int j = 0; j < 8; j++) o2[j] = 0ull;
    const u64* vb3 = (const u64*)(vsm + h * 1024);
    #pragma unroll
    for (int kp = 0; kp < 64; kp++) {
        u64 w2 = bc2(a[kp] * gq * gsm[kp]);
        const u64* vr = vb3 + kp * 8;
        #pragma unroll
        for (int j = 0; j < 8; j++) fma2(o2[j], w2, vr[j]);
    }
    #pragma unroll
    for (int j = 0; j < 8; j++) {
        float2 ov = upk(o2[j]);
        int c0 = h * 16 + 2 * j;
        osm[c0 * 64 + qp]       = ov.x + xw[c0 * 64 + qp];
        osm[(c0 + 1) * 64 + qp] = ov.y + xw[(c0 + 1) * 64 + qp];
    }
    __syncthreads();

    float* ob = g_out1 + ((size_t)cls * CN) * HWSZ;
    for (int id = tid; id < 512; id += 256) {
        int ch = id >> 3, i = id & 7;
        const float* src = osm + ch * 64 + i * 8;
        float4 a4 = {src[0], src[1], src[2], src[3]};
        float4 b4 = {src[4], src[5], src[6], src[7]};
        float* p = ob + (size_t)ch * HWSZ + (wy * 8 + i) * HH + wx * 8;
        *(float4*)p = a4;
        *(float4*)(p + 4) = b4;
    }
}

// ---------------------------------------------------------------------------
// K4: sum of M conv3x3-BN-relu6, packed f32x2 (8 pixel pairs per thread).
// ---------------------------------------------------------------------------
template <int M>
__global__ __launch_bounds__(256, 2)
void k_conv3(int src_id, int dst_id,
             const float* __restrict__ w, const float* __restrict__ s,
             const float* __restrict__ b, int m0) {
    int cls = blockIdx.z;
    int tx0 = blockIdx.x * 16, ty0 = blockIdx.y * 4;
    const float* src = (src_id == 0 ? g_out1 : g_x112) + (size_t)cls * CN * HWSZ;
    float* dst = (dst_id == 1 ? g_x112 : g_x223) + (size_t)cls * CN * HWSZ;
    extern __shared__ float sm[];
    float* ism = sm;            // 64*6*18 = 6912
    float* wsm = ism + 6912;    // M*64*73
    int tid = threadIdx.x;
    int oc = tid & 63, grp = tid >> 6;

    for (int id = tid; id < 6912; id += 256) {
        int c = id / 108, rem = id - c * 108;
        int r = rem / 18, col = rem - r * 18;
        int gy = ty0 + r - 1, gx = tx0 + col - 1;
        float v = 0.f;
        if ((unsigned)gy < 256u && (unsigned)gx < 256u)
            v = src[(size_t)c * HWSZ + gy * HH + gx];
        ism[id] = v;
    }
    const float* wbase = w + ((size_t)cls * 6 + m0) * 36864;
    u64 acc[M][8];
    #pragma unroll
    for (int m = 0; m < M; m++)
        #pragma unroll
        for (int j = 0; j < 8; j++) acc[m][j] = 0ull;

    for (int cc = 0; cc < 64; cc += 8) {
        __syncthreads();
        for (int id = tid; id < M * 64 * 72; id += 256) {
            int mo = id / 72, i = id - mo * 72;
            wsm[mo * 73 + i] = wbase[mo * 576 + cc * 9 + i];
        }
        __syncthreads();
        for (int c = 0; c < 8; c++) {
            const float* ib = ism + (cc + c) * 108 + grp * 18;
            #pragma unroll
            for (int ky = 0; ky < 3; ky++) {
                const float2* ir = (const float2*)(ib + ky * 18);
                float2 e2[9];
                #pragma unroll
                for (int j = 0; j < 9; j++) e2[j] = ir[j];
                u64 e[9], o[8];
                #pragma unroll
                for (int j = 0; j < 9; j++) e[j] = pk2(e2[j].x, e2[j].y);
                #pragma unroll
                for (int j = 0; j < 8; j++) o[j] = pk2(e2[j].y, e2[j + 1].x);
                #pragma unroll
                for (int m = 0; m < M; m++) {
                    const float* wp = wsm + (m * 64 + oc) * 73 + c * 9 + ky * 3;
                    u64 w0 = bc2(wp[0]), w1 = bc2(wp[1]), w2 = bc2(wp[2]);
                    #pragma unroll
                    for (int j = 0; j < 8; j++) {
                        fma2(acc[m][j], w0, e[j]);
                        fma2(acc[m][j], w1, o[j]);
                        fma2(acc[m][j], w2, e[j + 1]);
                    }
                }
            }
        }
    }

    float res[16];
    #pragma unroll
    for (int xx = 0; xx < 16; xx++) res[xx] = 0.f;
    #pragma unroll
    for (int m = 0; m < M; m++) {
        float sv = s[((size_t)cls * 6 + m0 + m) * 64 + oc];
        float bv = b[((size_t)cls * 6 + m0 + m) * 64 + oc];
        #pragma unroll
        for (int j = 0; j < 8; j++) {
            float2 v = upk(acc[m][j]);
            res[2 * j]     += fminf(fmaxf(v.x * sv + bv, 0.f), 6.f);
            res[2 * j + 1] += fminf(fmaxf(v.y * sv + bv, 0.f), 6.f);
        }
    }
    __syncthreads();
    float* osm = wsm;   // reuse
    #pragma unroll
    for (int xx = 0; xx < 16; xx++) osm[oc * 65 + grp * 16 + xx] = res[xx];
    __syncthreads();
    for (int id = tid; id < 1024; id += 256) {
        int oc2 = id >> 4, rq = id & 15, r = rq >> 2, qx = rq & 3;
        const float* sp = osm + oc2 * 65 + r * 16 + qx * 4;
        float4 v = {sp[0], sp[1], sp[2], sp[3]};
        *(float4*)(dst + (size_t)oc2 * HWSZ + (ty0 + r) * HH + tx0 + qx * 4) = v;
    }
}

// ---------------------------------------------------------------------------
// K5: x33 = conv3x3(x223) + concat 1x1-BN + residual + relu (packed f32x2).
// ---------------------------------------------------------------------------
__global__ __launch_bounds__(256)
void k_final(const float* __restrict__ w, const float* __restrict__ s,
             const float* __restrict__ b,
             const float* __restrict__ catw, const float* __restrict__ cats,
             const float* __restrict__ catb, float* __restrict__ out) {
    int cls = blockIdx.z;
    int tx0 = blockIdx.x * 16, ty0 = blockIdx.y * 4;
    const float* src  = g_x223 + (size_t)cls * CN * HWSZ;
    const float* x112 = g_x112 + (size_t)cls * CN * HWSZ;
    const float* out1 = g_out1 + (size_t)cls * CN * HWSZ;
    extern __shared__ float sm[];
    float* ism  = sm;              // 6912   (x223 tile + halo)
    float* wsm  = ism + 6912;      // 64*73 = 4672
    float* cwsm = wsm + 4672;      // 64*193 = 12352
    float* x1sm = cwsm + 12352;    // 4096
    float* x2sm = x1sm + 4096;     // 4096 (x223 center, aligned)
    float* x3sm = x2sm + 4096;     // 64*66 = 4224
    float* osm  = x3sm + 4224;     // 64*65 = 4160
    int tid = threadIdx.x;
    int oc = tid & 63, grp = tid >> 6;

    for (int id = tid; id < 6912; id += 256) {
        int c = id / 108, rem = id - c * 108;
        int r = rem / 18, col = rem - r * 18;
        int gy = ty0 + r - 1, gx = tx0 + col - 1;
        float v = 0.f;
        if ((unsigned)gy < 256u && (unsigned)gx < 256u)
            v = src[(size_t)c * HWSZ + gy * HH + gx];
        ism[id] = v;
    }
    for (int id = tid; id < 4096; id += 256) {
        int c = id >> 6, px = id & 63, r = px >> 4, col = px & 15;
        x1sm[id] = x112[(size_t)c * HWSZ + (ty0 + r) * HH + tx0 + col];
        x2sm[id] = src[(size_t)c * HWSZ + (ty0 + r) * HH + tx0 + col];
    }
    const float* cwb = catw + (size_t)cls * 64 * 192;
    for (int id = tid; id < 64 * 192; id += 256) {
        int o2 = id / 192, c2 = id - o2 * 192;
        cwsm[o2 * 193 + c2] = cwb[id];
    }
    const float* wbase = w + ((size_t)cls * 6 + 5) * 36864;
    u64 acc[8];
    #pragma unroll
    for (int j = 0; j < 8; j++) acc[j] = 0ull;

    for (int cc = 0; cc < 64; cc += 8) {
        __syncthreads();
        for (int id = tid; id < 64 * 72; id += 256) {
            int mo = id / 72, i = id - mo * 72;
            wsm[mo * 73 + i] = wbase[mo * 576 + cc * 9 + i];
        }
        __syncthreads();
        for (int c = 0; c < 8; c++) {
            const float* ib = ism + (cc + c) * 108 + grp * 18;
            #pragma unroll
            for (int ky = 0; ky < 3; ky++) {
                const float2* ir = (const float2*)(ib + ky * 18);
                float2 e2[9];
                #pragma unroll
                for (int j = 0; j < 9; j++) e2[j] = ir[j];
                u64 e[9], o[8];
                #pragma unroll
                for (int j = 0; j < 9; j++) e[j] = pk2(e2[j].x, e2[j].y);
                #pragma unroll
                for (int j = 0; j < 8; j++) o[j] = pk2(e2[j].y, e2[j + 1].x);
                const float* wp = wsm + oc * 73 + c * 9 + ky * 3;
                u64 w0 = bc2(wp[0]), w1 = bc2(wp[1]), w2 = bc2(wp[2]);
                #pragma unroll
                for (int j = 0; j < 8; j++) {
                    fma2(acc[j], w0, e[j]);
                    fma2(acc[j], w1, o[j]);
                    fma2(acc[j], w2, e[j + 1]);
                }
            }
        }
    }
    float sv = s[((size_t)cls * 6 + 5) * 64 + oc];
    float bv = b[((size_t)cls * 6 + 5) * 64 + oc];
    #pragma unroll
    for (int j = 0; j < 8; j++) {
        float2 v = upk(acc[j]);
        x3sm[oc * 66 + grp * 16 + 2 * j]     = fminf(fmaxf(v.x * sv + bv, 0.f), 6.f);
        x3sm[oc * 66 + grp * 16 + 2 * j + 1] = fminf(fmaxf(v.y * sv + bv, 0.f), 6.f);
    }
    __syncthreads();

    // 1x1 over [x112, x223, x33]: thread = (oc pair, 8-px group), packed
    {
        int ocp = tid >> 3;          // 0..31 -> oc {2*ocp, 2*ocp+1}
        int px0 = (tid & 7) * 8;     // 4 pairs
        u64 y[2][4];
        #pragma unroll
        for (int r = 0; r < 2; r++)
            #pragma unroll
            for (int j = 0; j < 4; j++) y[r][j] = 0ull;
        const float* cw0 = cwsm + (2 * ocp) * 193;
        const float* cw1 = cwsm + (2 * ocp + 1) * 193;
        #pragma unroll 2
        for (int c = 0; c < 64; c++) {
            const u64* p1 = (const u64*)(x1sm + c * 64 + px0);
            const u64* p2 = (const u64*)(x2sm + c * 64 + px0);
            const u64* p3 = (const u64*)(x3sm + c * 66 + px0);
            u64 wa1 = bc2(cw0[c]),       wb1 = bc2(cw1[c]);
            u64 wa2 = bc2(cw0[64 + c]),  wb2 = bc2(cw1[64 + c]);
            u64 wa3 = bc2(cw0[128 + c]), wb3 = bc2(cw1[128 + c]);
            #pragma unroll
            for (int j = 0; j < 4; j++) {
                u64 v1 = p1[j], v2 = p2[j], v3 = p3[j];
                fma2(y[0][j], wa1, v1);
                fma2(y[1][j], wb1, v1);
                fma2(y[0][j], wa2, v2);
                fma2(y[1][j], wb2, v2);
                fma2(y[0][j], wa3, v3);
                fma2(y[1][j], wb3, v3);
            }
        }
        #pragma unroll
        for (int r = 0; r < 2; r++) {
            int o2 = 2 * ocp + r;
            float csv = cats[cls * 64 + o2], cbv = catb[cls * 64 + o2];
            #pragma unroll
            for (int j = 0; j < 4; j++) {
                float2 v = upk(y[r][j]);
                osm[o2 * 65 + px0 + 2 * j]     = v.x * csv + cbv;
                osm[o2 * 65 + px0 + 2 * j + 1] = v.y * csv + cbv;
            }
        }
    }
    __syncthreads();

    float* ob = out + ((size_t)cls * CN) * HWSZ;
    for (int id = tid; id < 1024; id += 256) {
        int oc2 = id >> 4, rq = id & 15, r = rq >> 2, qx = rq & 3;
        const float* sp = osm + oc2 * 65 + r * 16 + qx * 4;
        const float* rp = out1 + (size_t)oc2 * HWSZ + (ty0 + r) * HH + tx0 + qx * 4;
        float4 rv = *(const float4*)rp;
        float4 v;
        v.x = fmaxf(sp[0] + rv.x, 0.f);
        v.y = fmaxf(sp[1] + rv.y, 0.f);
        v.z = fmaxf(sp[2] + rv.z, 0.f);
        v.w = fmaxf(sp[3] + rv.w, 0.f);
        *(float4*)(ob + (size_t)oc2 * HWSZ + (ty0 + r) * HH + tx0 + qx * 4) = v;
    }
}

// ---------------------------------------------------------------------------
extern "C" void kernel_launch(void* const* d_in, const int* in_sizes, int n_in,
                              void* d_out, int out_size) {
    const float* x    = (const float*)d_in[0];
    const float* qkw  = (const float*)d_in[1];
    const float* qks  = (const float*)d_in[2];
    const float* qkb  = (const float*)d_in[3];
    const float* relb = (const float*)d_in[4];
    const float* wvw  = (const float*)d_in[5];
    const float* wvs  = (const float*)d_in[6];
    const float* wvb  = (const float*)d_in[7];
    const float* mmsw = (const float*)d_in[8];
    const float* mmss = (const float*)d_in[9];
    const float* mmsb = (const float*)d_in[10];
    const float* catw = (const float*)d_in[11];
    const float* cats = (const float*)d_in[12];
    const float* catb = (const float*)d_in[13];
    float* out = (float*)d_out;

    const int SM_MASK = (4096 + 8320 + 8320 + 4096 + 64 + 900) * 4;       // 103184
    const int SM_ATTN = (4096 + 4160 + 4096 + 4096 + 4160 + 900 + 64 + 4096) * 4; // 102672
    const int SM_C3   = (6912 + 3 * 64 * 73) * 4;                          // 83712
    const int SM_C2   = (6912 + 2 * 64 * 73) * 4;                          // 65024
    const int SM_FIN  = (6912 + 4672 + 12352 + 4096 + 4096 + 4224 + 4160) * 4; // 162048

    cudaFuncSetAttribute(k_mask,     cudaFuncAttributeMaxDynamicSharedMemorySize, SM_MASK);
    cudaFuncSetAttribute(k_attn,     cudaFuncAttributeMaxDynamicSharedMemorySize, SM_ATTN);
    cudaFuncSetAttribute(k_conv3<3>, cudaFuncAttributeMaxDynamicSharedMemorySize, SM_C3);
    cudaFuncSetAttribute(k_conv3<2>, cudaFuncAttributeMaxDynamicSharedMemorySize, SM_C2);
    cudaFuncSetAttribute(k_final,    cudaFuncAttributeMaxDynamicSharedMemorySize, SM_FIN);

    k_mask<<<dim3(NWIN, NCLS), 256, SM_MASK>>>(x, qkw, qks, qkb, relb);
    k_good<<<256, 256>>>();
    k_attn<<<dim3(NWIN, NCLS), 256, SM_ATTN>>>(x, relb, wvw, wvs, wvb);
    dim3 cg(16, 64, NCLS);
    k_conv3<3><<<cg, 256, SM_C3>>>(0, 1, mmsw, mmss, mmsb, 0);
    k_conv3<2><<<cg, 256, SM_C2>>>(1, 2, mmsw, mmss, mmsb, 3);
    k_final<<<cg, 256, SM_FIN>>>(mmsw, mmss, mmsb, catw, cats, catb, out);
}

// round 5
// speedup vs baseline: 1.1452x; 1.1452x over previous
#include <cuda_runtime.h>

#define CN    64
#define HH    256
#define HWSZ  65536
#define NCLS  6
#define NWIN  1024

typedef unsigned long long u64;

__device__ __forceinline__ u64 pk2(float lo, float hi) {
    u64 r; asm("mov.b64 %0, {%1, %2};" : "=l"(r) : "f"(lo), "f"(hi)); return r;
}
__device__ __forceinline__ u64 bc2(float v) { return pk2(v, v); }
__device__ __forceinline__ void fma2(u64& a, u64 x, u64 y) {
    asm("fma.rn.f32x2 %0, %1, %2, %0;" : "+l"(a) : "l"(x), "l"(y));
}
__device__ __forceinline__ float2 upk(u64 v) {
    float2 r; asm("mov.b64 {%0, %1}, %2;" : "=f"(r.x), "=f"(r.y) : "l"(v)); return r;
}

// ---------------- scratch (device globals; no allocations allowed) ----------
__device__ float g_mask[NCLS * NWIN * 64];
__device__ float g_good[NCLS * NWIN * 64];
__device__ float g_qk[(size_t)NCLS * NWIN * 8192];    // per-window q (4096) + k (4096)
__device__ float g_out1[(size_t)NCLS * CN * HWSZ];    // x + class_attn
__device__ float g_x112[(size_t)NCLS * CN * HWSZ];
__device__ float g_x223[(size_t)NCLS * CN * HWSZ];

// ---------------------------------------------------------------------------
// K1: qk conv (packed f32x2) + mask; stores q/k for reuse by k_attn.
// ---------------------------------------------------------------------------
__global__ __launch_bounds__(256)
void k_mask(const float* __restrict__ x, const float* __restrict__ qkw,
            const float* __restrict__ qks, const float* __restrict__ qkb,
            const float* __restrict__ relb) {
    int cls = blockIdx.y, win = blockIdx.x;
    int wy = win >> 5, wx = win & 31;
    extern __shared__ float sm[];
    float* xw   = sm;            // 4096
    float* wsm  = xw + 4096;     // 128*65 = 8320
    float* qk   = wsm + 8320;    // 128*65 = 8320
    float* kl   = qk + 8320;     // 4096  (k in [h][px][d])
    float* qsum = kl + 4096;     // 64
    float* rsm  = qsum + 64;     // 900
    int tid = threadIdx.x;
    const float* xb = x + ((size_t)cls * CN) * HWSZ;

    for (int id = tid; id < 512; id += 256) {
        int ch = id >> 3, i = id & 7;
        const float* p = xb + (size_t)ch * HWSZ + (wy * 8 + i) * HH + wx * 8;
        float4 a = *(const float4*)p;
        float4 b = *(const float4*)(p + 4);
        float* d = xw + ch * 64 + i * 8;
        d[0]=a.x; d[1]=a.y; d[2]=a.z; d[3]=a.w;
        d[4]=b.x; d[5]=b.y; d[6]=b.z; d[7]=b.w;
    }
    const float* wb = qkw + (size_t)cls * 8192;
    for (int id = tid; id < 8192; id += 256)
        wsm[(id >> 6) * 65 + (id & 63)] = wb[id];
    const float* rb = relb + cls * 900;
    for (int id = tid; id < 900; id += 256) rsm[id] = rb[id];
    __syncthreads();

    const float* sS = qks + cls * 128;
    const float* sB = qkb + cls * 128;
    {
        int ocp = tid >> 2;          // oc {2*ocp, 2*ocp+1}
        int px0 = (tid & 3) * 16;
        u64 acc[2][8];
        #pragma unroll
        for (int r = 0; r < 2; r++)
            #pragma unroll
            for (int j = 0; j < 8; j++) acc[r][j] = 0ull;
        const float* w0r = wsm + (2 * ocp) * 65;
        const float* w1r = wsm + (2 * ocp + 1) * 65;
        #pragma unroll 4
        for (int c = 0; c < 64; c++) {
            u64 wa = bc2(w0r[c]);
            u64 wb2 = bc2(w1r[c]);
            const u64* xp = (const u64*)(xw + c * 64 + px0);
            #pragma unroll
            for (int j = 0; j < 8; j++) {
                u64 x2 = xp[j];
                fma2(acc[0][j], wa, x2);
                fma2(acc[1][j], wb2, x2);
            }
        }
        #pragma unroll
        for (int r = 0; r < 2; r++) {
            int oc = 2 * ocp + r;
            float s = sS[oc], b = sB[oc];
            #pragma unroll
            for (int j = 0; j < 8; j++) {
                float2 v = upk(acc[r][j]);
                qk[oc * 65 + px0 + 2 * j]     = fmaxf(v.x * s + b, 0.f);
                qk[oc * 65 + px0 + 2 * j + 1] = fmaxf(v.y * s + b, 0.f);
            }
        }
    }
    __syncthreads();

    float* gbase = g_qk + (size_t)(cls * NWIN + win) * 8192;
    for (int id = tid; id < 4096; id += 256) {
        int h = id >> 10, rem = id & 1023, px = rem >> 4, d = rem & 15;
        kl[id] = qk[(64 + h * 16 + d) * 65 + px];
    }
    for (int id = tid; id < 4096; id += 256)
        gbase[id] = qk[(id >> 6) * 65 + (id & 63)];
    if (tid < 64) {
        float s = 0.f;
        const float* r = qk + tid * 65;
        #pragma unroll 16
        for (int p = 0; p < 64; p++) s += r[p];
        qsum[tid] = s;
    }
    __syncthreads();

    {
        float4* gk4 = (float4*)(gbase + 4096);
        const float4* kl4 = (const float4*)kl;
        for (int id = tid; id < 1024; id += 256) gk4[id] = kl4[id];
    }

    if (tid < 64) {
        int kp = tid, ik = kp >> 3, jk = kp & 7;
        float dot = 0.f;
        #pragma unroll 16
        for (int ch = 0; ch < 64; ch++) dot += qsum[ch] * qk[(64 + ch) * 65 + kp];
        float rbv = 0.f;
        for (int q = 0; q < 64; q++) {
            int ridx = ((q >> 3) - ik + 7) * 15 + ((q & 7) - jk + 7);
            const float* r4 = rsm + ridx * 4;
            rbv += r4[0] + r4[1] + r4[2] + r4[3];
        }
        g_mask[(cls * NWIN + win) * 64 + kp] = dot * (0.25f / 256.f) + rbv * (1.f / 256.f);
    }
}

// ---------------------------------------------------------------------------
__global__ void k_good() {
    int i = blockIdx.x * 256 + threadIdx.x;
    float m[NCLS], mx = -1e30f;
    #pragma unroll
    for (int c = 0; c < NCLS; c++) {
        m[c] = g_mask[c * NWIN * 64 + i];
        mx = fmaxf(mx, m[c]);
    }
    #pragma unroll
    for (int c = 0; c < NCLS; c++)
        g_good[c * NWIN * 64 + i] = (m[c] == mx) ? 1.f : -1.f;
}

// ---------------------------------------------------------------------------
// K3: attention (loads q/k from g_qk), v conv, softmax, mask, attn@v,
//     residual + un-window.
// ---------------------------------------------------------------------------
__global__ __launch_bounds__(256)
void k_attn(const float* __restrict__ x, const float* __restrict__ relb,
            const float* __restrict__ wvw, const float* __restrict__ wvs,
            const float* __restrict__ wvb) {
    int cls = blockIdx.y, win = blockIdx.x;
    int wy = win >> 5, wx = win & 31;
    extern __shared__ float sm[];
    float* xw  = sm;             // 4096
    float* qsm = xw + 4096;      // 4160
    float* ksm = qsm + 4160;     // 4096 [h][px][d]
    float* vsm = ksm + 4096;     // 4096 [h][px][d]
    float* wsm = vsm + 4096;     // 4160
    float* rsm = wsm + 4160;     // 900
    float* gsm = rsm + 900;      // 64
    float* osm = gsm + 64;       // 4096
    int tid = threadIdx.x;
    const float* xb = x + ((size_t)cls * CN) * HWSZ;

    for (int id = tid; id < 512; id += 256) {
        int ch = id >> 3, i = id & 7;
        const float* p = xb + (size_t)ch * HWSZ + (wy * 8 + i) * HH + wx * 8;
        float4 a = *(const float4*)p;
        float4 b = *(const float4*)(p + 4);
        float* d = xw + ch * 64 + i * 8;
        d[0]=a.x; d[1]=a.y; d[2]=a.z; d[3]=a.w;
        d[4]=b.x; d[5]=b.y; d[6]=b.z; d[7]=b.w;
    }
    const float* gbase = g_qk + (size_t)(cls * NWIN + win) * 8192;
    for (int id = tid; id < 4096; id += 256)
        qsm[(id >> 6) * 65 + (id & 63)] = gbase[id];
    {
        const float4* gk4 = (const float4*)(gbase + 4096);
        float4* k4 = (float4*)ksm;
        for (int id = tid; id < 1024; id += 256) k4[id] = gk4[id];
    }
    const float* wvwb = wvw + (size_t)cls * 4096;
    for (int id = tid; id < 4096; id += 256)
        wsm[(id >> 6) * 65 + (id & 63)] = wvwb[id];
    const float* rb = relb + cls * 900;
    for (int id = tid; id < 900; id += 256) rsm[id] = rb[id];
    if (tid < 64) gsm[tid] = g_good[(cls * NWIN + win) * 64 + tid];
    __syncthreads();

    // v conv
    {
        int ocp = tid >> 3;
        int px0 = (tid & 7) * 8;
        u64 acc[2][4];
        #pragma unroll
        for (int r = 0; r < 2; r++)
            #pragma unroll
            for (int j = 0; j < 4; j++) acc[r][j] = 0ull;
        const float* w0r = wsm + (2 * ocp) * 65;
        const float* w1r = wsm + (2 * ocp + 1) * 65;
        #pragma unroll 4
        for (int c = 0; c < 64; c++) {
            u64 wa = bc2(w0r[c]);
            u64 wb2 = bc2(w1r[c]);
            const u64* xp = (const u64*)(xw + c * 64 + px0);
            #pragma unroll
            for (int j = 0; j < 4; j++) {
                u64 x2 = xp[j];
                fma2(acc[0][j], wa, x2);
                fma2(acc[1][j], wb2, x2);
            }
        }
        const float* vS = wvs + cls * 64;
        const float* vB = wvb + cls * 64;
        #pragma unroll
        for (int r = 0; r < 2; r++) {
            int oc = 2 * ocp + r;
            int h = oc >> 4, d = oc & 15;
            float s = vS[oc], b = vB[oc];
            #pragma unroll
            for (int j = 0; j < 4; j++) {
                float2 v = upk(acc[r][j]);
                vsm[h * 1024 + (px0 + 2 * j) * 16 + d]     = fmaxf(v.x * s + b, 0.f);
                vsm[h * 1024 + (px0 + 2 * j + 1) * 16 + d] = fmaxf(v.y * s + b, 0.f);
            }
        }
    }
    __syncthreads();

    int h = tid >> 6, qp = tid & 63;
    int iq = qp >> 3, jq = qp & 7;
    u64 q2[8];
    #pragma unroll
    for (int j = 0; j < 8; j++)
        q2[j] = pk2(qsm[(h * 16 + 2 * j) * 65 + qp], qsm[(h * 16 + 2 * j + 1) * 65 + qp]);

    float a[64];
    const u64* kb2 = (const u64*)(ksm + h * 1024);
    #pragma unroll
    for (int kp = 0; kp < 64; kp++) {
        const u64* kr = kb2 + kp * 8;
        u64 dacc = 0ull;
        #pragma unroll
        for (int j = 0; j < 8; j++) fma2(dacc, q2[j], kr[j]);
        float2 dv = upk(dacc);
        int ridx = (iq - (kp >> 3) + 7) * 15 + (jq - (kp & 7) + 7);
        a[kp] = (dv.x + dv.y) * 0.25f + rsm[ridx * 4 + h];
    }
    float mx = -1e30f;
    #pragma unroll
    for (int kp = 0; kp < 64; kp++) mx = fmaxf(mx, a[kp]);
    float ssum = 0.f;
    #pragma unroll
    for (int kp = 0; kp < 64; kp++) { a[kp] = __expf(a[kp] - mx); ssum += a[kp]; }
    float gq = gsm[qp] / ssum;

    u64 o2[8];
    #pragma unroll
    for (int j = 0; j < 8; j++) o2[j] = 0ull;
    const u64* vb3 = (const u64*)(vsm + h * 1024);
    #pragma unroll
    for (int kp = 0; kp < 64; kp++) {
        u64 w2 = bc2(a[kp] * gq * gsm[kp]);
        const u64* vr = vb3 + kp * 8;
        #pragma unroll
        for (int j = 0; j < 8; j++) fma2(o2[j], w2, vr[j]);
    }
    #pragma unroll
    for (int j = 0; j < 8; j++) {
        float2 ov = upk(o2[j]);
        int c0 = h * 16 + 2 * j;
        osm[c0 * 64 + qp]       = ov.x + xw[c0 * 64 + qp];
        osm[(c0 + 1) * 64 + qp] = ov.y + xw[(c0 + 1) * 64 + qp];
    }
    __syncthreads();

    float* ob = g_out1 + ((size_t)cls * CN) * HWSZ;
    for (int id = tid; id < 512; id += 256) {
        int ch = id >> 3, i = id & 7;
        const float* src = osm + ch * 64 + i * 8;
        float4 a4 = {src[0], src[1], src[2], src[3]};
        float4 b4 = {src[4], src[5], src[6], src[7]};
        float* p = ob + (size_t)ch * HWSZ + (wy * 8 + i) * HH + wx * 8;
        *(float4*)p = a4;
        *(float4*)(p + 4) = b4;
    }
}

// ---------------------------------------------------------------------------
// Interleaved halo loader: per (c, halo row r), 20 floats: slot p -> col
// (p>>1) + 8*(p&1). P[j]=(x[j], x[j+8]) as aligned u64. Cols 8,9 dual-stored.
// ---------------------------------------------------------------------------
__device__ __forceinline__ void load_halo_ilv(float* ism, const float* src,
                                              int tx0, int ty0, int tid) {
    for (int id = tid; id < 7680; id += 256) {
        int c = id / 120, rem = id - c * 120;
        int r = rem / 20, p = rem - r * 20;
        int col = (p >> 1) + 8 * (p & 1);
        int gy = ty0 + r - 1, gx = tx0 + col - 1;
        float v = 0.f;
        if ((unsigned)gy < 256u && (unsigned)gx < 256u)
            v = src[(size_t)c * HWSZ + gy * HH + gx];
        ism[id] = v;
    }
}

// ---------------------------------------------------------------------------
// K4: sum of M conv3x3-BN-relu6, f32x2 with interleaved pairs (px, px+8):
// every tap is one aligned broadcast LDS.64, zero repacking.
// ---------------------------------------------------------------------------
template <int M>
__global__ __launch_bounds__(256, 2)
void k_conv3(int src_id, int dst_id,
             const float* __restrict__ w, const float* __restrict__ s,
             const float* __restrict__ b, int m0) {
    int cls = blockIdx.z;
    int tx0 = blockIdx.x * 16, ty0 = blockIdx.y * 4;
    const float* src = (src_id == 0 ? g_out1 : g_x112) + (size_t)cls * CN * HWSZ;
    float* dst = (dst_id == 1 ? g_x112 : g_x223) + (size_t)cls * CN * HWSZ;
    extern __shared__ float sm[];
    float* ism = sm;            // 64*6*20 = 7680 (interleaved)
    float* wsm = ism + 7680;    // M*64*73
    int tid = threadIdx.x;
    int oc = tid & 63, grp = tid >> 6;

    load_halo_ilv(ism, src, tx0, ty0, tid);

    const float* wbase = w + ((size_t)cls * 6 + m0) * 36864;
    u64 acc[M][8];
    #pragma unroll
    for (int m = 0; m < M; m++)
        #pragma unroll
        for (int j = 0; j < 8; j++) acc[m][j] = 0ull;

    for (int cc = 0; cc < 64; cc += 8) {
        __syncthreads();
        for (int id = tid; id < M * 64 * 72; id += 256) {
            int mo = id / 72, i = id - mo * 72;
            wsm[mo * 73 + i] = wbase[mo * 576 + cc * 9 + i];
        }
        __syncthreads();
        for (int c = 0; c < 8; c++) {
            const float* ib = ism + (cc + c) * 120 + grp * 20;
            #pragma unroll
            for (int ky = 0; ky < 3; ky++) {
                const u64* P = (const u64*)(ib + ky * 20);
                u64 p[10];
                #pragma unroll
                for (int j = 0; j < 10; j++) p[j] = P[j];
                #pragma unroll
                for (int m = 0; m < M; m++) {
                    const float* wp = wsm + (m * 64 + oc) * 73 + c * 9 + ky * 3;
                    u64 w0 = bc2(wp[0]), w1 = bc2(wp[1]), w2 = bc2(wp[2]);
                    #pragma unroll
                    for (int j = 0; j < 8; j++) {
                        fma2(acc[m][j], w0, p[j]);
                        fma2(acc[m][j], w1, p[j + 1]);
                        fma2(acc[m][j], w2, p[j + 2]);
                    }
                }
            }
        }
    }

    float res[16];
    #pragma unroll
    for (int xx = 0; xx < 16; xx++) res[xx] = 0.f;
    #pragma unroll
    for (int m = 0; m < M; m++) {
        float sv = s[((size_t)cls * 6 + m0 + m) * 64 + oc];
        float bv = b[((size_t)cls * 6 + m0 + m) * 64 + oc];
        #pragma unroll
        for (int j = 0; j < 8; j++) {
            float2 v = upk(acc[m][j]);
            res[j]     += fminf(fmaxf(v.x * sv + bv, 0.f), 6.f);
            res[j + 8] += fminf(fmaxf(v.y * sv + bv, 0.f), 6.f);
        }
    }
    __syncthreads();
    float* osm = wsm;   // reuse
    #pragma unroll
    for (int xx = 0; xx < 16; xx++) osm[oc * 65 + grp * 16 + xx] = res[xx];
    __syncthreads();
    for (int id = tid; id < 1024; id += 256) {
        int oc2 = id >> 4, rq = id & 15, r = rq >> 2, qx = rq & 3;
        const float* sp = osm + oc2 * 65 + r * 16 + qx * 4;
        float4 v = {sp[0], sp[1], sp[2], sp[3]};
        *(float4*)(dst + (size_t)oc2 * HWSZ + (ty0 + r) * HH + tx0 + qx * 4) = v;
    }
}

// ---------------------------------------------------------------------------
// K5: x33 = conv3x3(x223) (interleaved f32x2) + concat 1x1-BN + residual + relu.
// ---------------------------------------------------------------------------
__global__ __launch_bounds__(256)
void k_final(const float* __restrict__ w, const float* __restrict__ s,
             const float* __restrict__ b,
             const float* __restrict__ catw, const float* __restrict__ cats,
             const float* __restrict__ catb, float* __restrict__ out) {
    int cls = blockIdx.z;
    int tx0 = blockIdx.x * 16, ty0 = blockIdx.y * 4;
    const float* src  = g_x223 + (size_t)cls * CN * HWSZ;
    const float* x112 = g_x112 + (size_t)cls * CN * HWSZ;
    const float* out1 = g_out1 + (size_t)cls * CN * HWSZ;
    extern __shared__ float sm[];
    float* ism  = sm;              // 7680 interleaved x223 halo
    float* wsm  = ism + 7680;      // 64*73 = 4672
    float* cwsm = wsm + 4672;      // 64*193 = 12352
    float* x1sm = cwsm + 12352;    // 4096
    float* x2sm = x1sm + 4096;     // 4096 (x223 center, linear)
    float* x3sm = x2sm + 4096;     // 64*66 = 4224
    float* osm  = x3sm + 4224;     // 64*65 = 4160
    int tid = threadIdx.x;
    int oc = tid & 63, grp = tid >> 6;

    load_halo_ilv(ism, src, tx0, ty0, tid);
    for (int id = tid; id < 4096; id += 256) {
        int c = id >> 6, px = id & 63, r = px >> 4, col = px & 15;
        x1sm[id] = x112[(size_t)c * HWSZ + (ty0 + r) * HH + tx0 + col];
        x2sm[id] = src[(size_t)c * HWSZ + (ty0 + r) * HH + tx0 + col];
    }
    const float* cwb = catw + (size_t)cls * 64 * 192;
    for (int id = tid; id < 64 * 192; id += 256) {
        int o2 = id / 192, c2 = id - o2 * 192;
        cwsm[o2 * 193 + c2] = cwb[id];
    }
    const float* wbase = w + ((size_t)cls * 6 + 5) * 36864;
    u64 acc[8];
    #pragma unroll
    for (int j = 0; j < 8; j++) acc[j] = 0ull;

    for (int cc = 0; cc < 64; cc += 8) {
        __syncthreads();
        for (int id = tid; id < 64 * 72; id += 256) {
            int mo = id / 72, i = id - mo * 72;
            wsm[mo * 73 + i] = wbase[mo * 576 + cc * 9 + i];
        }
        __syncthreads();
        for (int c = 0; c < 8; c++) {
            const float* ib = ism + (cc + c) * 120 + grp * 20;
            #pragma unroll
            for (int ky = 0; ky < 3; ky++) {
                const u64* P = (const u64*)(ib + ky * 20);
                u64 p[10];
                #pragma unroll
                for (int j = 0; j < 10; j++) p[j] = P[j];
                const float* wp = wsm + oc * 73 + c * 9 + ky * 3;
                u64 w0 = bc2(wp[0]), w1 = bc2(wp[1]), w2 = bc2(wp[2]);
                #pragma unroll
                for (int j = 0; j < 8; j++) {
                    fma2(acc[j], w0, p[j]);
                    fma2(acc[j], w1, p[j + 1]);
                    fma2(acc[j], w2, p[j + 2]);
                }
            }
        }
    }
    float sv = s[((size_t)cls * 6 + 5) * 64 + oc];
    float bv = b[((size_t)cls * 6 + 5) * 64 + oc];
    #pragma unroll
    for (int j = 0; j < 8; j++) {
        float2 v = upk(acc[j]);
        x3sm[oc * 66 + grp * 16 + j]     = fminf(fmaxf(v.x * sv + bv, 0.f), 6.f);
        x3sm[oc * 66 + grp * 16 + j + 8] = fminf(fmaxf(v.y * sv + bv, 0.f), 6.f);
    }
    __syncthreads();

    // 1x1 over [x112, x223, x33]: thread = (oc pair, 8-px group), packed
    {
        int ocp = tid >> 3;
        int px0 = (tid & 7) * 8;
        u64 y[2][4];
        #pragma unroll
        for (int r = 0; r < 2; r++)
            #pragma unroll
            for (int j = 0; j < 4; j++) y[r][j] = 0ull;
        const float* cw0 = cwsm + (2 * ocp) * 193;
        const float* cw1 = cwsm + (2 * ocp + 1) * 193;
        #pragma unroll 2
        for (int c = 0; c < 64; c++) {
            const u64* p1 = (const u64*)(x1sm + c * 64 + px0);
            const u64* p2 = (const u64*)(x2sm + c * 64 + px0);
            const u64* p3 = (const u64*)(x3sm + c * 66 + px0);
            u64 wa1 = bc2(cw0[c]),       wb1 = bc2(cw1[c]);
            u64 wa2 = bc2(cw0[64 + c]),  wb2 = bc2(cw1[64 + c]);
            u64 wa3 = bc2(cw0[128 + c]), wb3 = bc2(cw1[128 + c]);
            #pragma unroll
            for (int j = 0; j < 4; j++) {
                u64 v1 = p1[j], v2 = p2[j], v3 = p3[j];
                fma2(y[0][j], wa1, v1);
                fma2(y[1][j], wb1, v1);
                fma2(y[0][j], wa2, v2);
                fma2(y[1][j], wb2, v2);
                fma2(y[0][j], wa3, v3);
                fma2(y[1][j], wb3, v3);
            }
        }
        #pragma unroll
        for (int r = 0; r < 2; r++) {
            int o2 = 2 * ocp + r;
            float csv = cats[cls * 64 + o2], cbv = catb[cls * 64 + o2];
            #pragma unroll
            for (int j = 0; j < 4; j++) {
                float2 v = upk(y[r][j]);
                osm[o2 * 65 + px0 + 2 * j]     = v.x * csv + cbv;
                osm[o2 * 65 + px0 + 2 * j + 1] = v.y * csv + cbv;
            }
        }
    }
    __syncthreads();

    float* ob = out + ((size_t)cls * CN) * HWSZ;
    for (int id = tid; id < 1024; id += 256) {
        int oc2 = id >> 4, rq = id & 15, r = rq >> 2, qx = rq & 3;
        const float* sp = osm + oc2 * 65 + r * 16 + qx * 4;
        const float* rp = out1 + (size_t)oc2 * HWSZ + (ty0 + r) * HH + tx0 + qx * 4;
        float4 rv = *(const float4*)rp;
        float4 v;
        v.x = fmaxf(sp[0] + rv.x, 0.f);
        v.y = fmaxf(sp[1] + rv.y, 0.f);
        v.z = fmaxf(sp[2] + rv.z, 0.f);
        v.w = fmaxf(sp[3] + rv.w, 0.f);
        *(float4*)(ob + (size_t)oc2 * HWSZ + (ty0 + r) * HH + tx0 + qx * 4) = v;
    }
}

// ---------------------------------------------------------------------------
extern "C" void kernel_launch(void* const* d_in, const int* in_sizes, int n_in,
                              void* d_out, int out_size) {
    const float* x    = (const float*)d_in[0];
    const float* qkw  = (const float*)d_in[1];
    const float* qks  = (const float*)d_in[2];
    const float* qkb  = (const float*)d_in[3];
    const float* relb = (const float*)d_in[4];
    const float* wvw  = (const float*)d_in[5];
    const float* wvs  = (const float*)d_in[6];
    const float* wvb  = (const float*)d_in[7];
    const float* mmsw = (const float*)d_in[8];
    const float* mmss = (const float*)d_in[9];
    const float* mmsb = (const float*)d_in[10];
    const float* catw = (const float*)d_in[11];
    const float* cats = (const float*)d_in[12];
    const float* catb = (const float*)d_in[13];
    float* out = (float*)d_out;

    const int SM_MASK = (4096 + 8320 + 8320 + 4096 + 64 + 900) * 4;
    const int SM_ATTN = (4096 + 4160 + 4096 + 4096 + 4160 + 900 + 64 + 4096) * 4;
    const int SM_C3   = (7680 + 3 * 64 * 73) * 4;   // 86784
    const int SM_C2   = (7680 + 2 * 64 * 73) * 4;   // 68096
    const int SM_FIN  = (7680 + 4672 + 12352 + 4096 + 4096 + 4224 + 4160) * 4; // 165120

    cudaFuncSetAttribute(k_mask,     cudaFuncAttributeMaxDynamicSharedMemorySize, SM_MASK);
    cudaFuncSetAttribute(k_attn,     cudaFuncAttributeMaxDynamicSharedMemorySize, SM_ATTN);
    cudaFuncSetAttribute(k_conv3<3>, cudaFuncAttributeMaxDynamicSharedMemorySize, SM_C3);
    cudaFuncSetAttribute(k_conv3<2>, cudaFuncAttributeMaxDynamicSharedMemorySize, SM_C2);
    cudaFuncSetAttribute(k_final,    cudaFuncAttributeMaxDynamicSharedMemorySize, SM_FIN);

    k_mask<<<dim3(NWIN, NCLS), 256, SM_MASK>>>(x, qkw, qks, qkb, relb);
    k_good<<<256, 256>>>();
    k_attn<<<dim3(NWIN, NCLS), 256, SM_ATTN>>>(x, relb, wvw, wvs, wvb);
    dim3 cg(16, 64, NCLS);
    k_conv3<3><<<cg, 256, SM_C3>>>(0, 1, mmsw, mmss, mmsb, 0);
    k_conv3<2><<<cg, 256, SM_C2>>>(1, 2, mmsw, mmss, mmsb, 3);
    k_final<<<cg, 256, SM_FIN>>>(mmsw, mmss, mmsb, catw, cats, catb, out);
}

// round 6
// speedup vs baseline: 1.4855x; 1.2971x over previous
#include <cuda_runtime.h>

#define CN    64
#define HH    256
#define HWSZ  65536
#define NCLS  6
#define NWIN  1024

typedef unsigned long long u64;

__device__ __forceinline__ u64 pk2(float lo, float hi) {
    u64 r; asm("mov.b64 %0, {%1, %2};" : "=l"(r) : "f"(lo), "f"(hi)); return r;
}
__device__ __forceinline__ u64 bc2(float v) { return pk2(v, v); }
__device__ __forceinline__ void fma2(u64& a, u64 x, u64 y) {
    asm("fma.rn.f32x2 %0, %1, %2, %0;" : "+l"(a) : "l"(x), "l"(y));
}
__device__ __forceinline__ float2 upk(u64 v) {
    float2 r; asm("mov.b64 {%0, %1}, %2;" : "=f"(r.x), "=f"(r.y) : "l"(v)); return r;
}
__device__ __forceinline__ void cpasync16(unsigned dst, const void* src) {
    asm volatile("cp.async.cg.shared.global [%0], [%1], 16;" :: "r"(dst), "l"(src));
}
__device__ __forceinline__ void cpcommit() {
    asm volatile("cp.async.commit_group;");
}
__device__ __forceinline__ void cpwait0() {
    asm volatile("cp.async.wait_group 0;" ::: "memory");
}

// ---------------- scratch (device globals; no allocations allowed) ----------
__device__ float g_mask[NCLS * NWIN * 64];
__device__ float g_good[NCLS * NWIN * 64];
__device__ float g_qk[(size_t)NCLS * NWIN * 8192];    // per-window q (4096) + k (4096)
__device__ float g_wT[NCLS * 6 * 576 * 64];           // transposed conv weights [cm][tap][oc]
__device__ float g_out1[(size_t)NCLS * CN * HWSZ];    // x + class_attn
__device__ float g_x112[(size_t)NCLS * CN * HWSZ];
__device__ float g_x223[(size_t)NCLS * CN * HWSZ];
__device__ float g_x33 [(size_t)NCLS * CN * HWSZ];

// ---------------------------------------------------------------------------
// K0: transpose conv weights -> [cls*6+m][tap(ic*9+ky*3+kx)][oc]
// ---------------------------------------------------------------------------
__global__ void k_prep(const float* __restrict__ w) {
    int id = blockIdx.x * 256 + threadIdx.x;
    if (id >= NCLS * 6 * 64 * 576) return;
    int cm = id / (64 * 576);
    int rem = id - cm * 64 * 576;
    int oc = rem / 576, tap = rem - oc * 576;
    g_wT[(cm * 576 + tap) * 64 + oc] = w[id];
}

// ---------------------------------------------------------------------------
// K1: qk conv (packed f32x2) + mask; stores q/k for reuse by k_attn.
// ---------------------------------------------------------------------------
__global__ __launch_bounds__(256)
void k_mask(const float* __restrict__ x, const float* __restrict__ qkw,
            const float* __restrict__ qks, const float* __restrict__ qkb,
            const float* __restrict__ relb) {
    int cls = blockIdx.y, win = blockIdx.x;
    int wy = win >> 5, wx = win & 31;
    extern __shared__ float sm[];
    float* xw   = sm;            // 4096
    float* wsm  = xw + 4096;     // 8320
    float* qk   = wsm + 8320;    // 8320
    float* kl   = qk + 8320;     // 4096
    float* qsum = kl + 4096;     // 64
    float* rsm  = qsum + 64;     // 900
    int tid = threadIdx.x;
    const float* xb = x + ((size_t)cls * CN) * HWSZ;

    for (int id = tid; id < 512; id += 256) {
        int ch = id >> 3, i = id & 7;
        const float* p = xb + (size_t)ch * HWSZ + (wy * 8 + i) * HH + wx * 8;
        float4 a = *(const float4*)p;
        float4 b = *(const float4*)(p + 4);
        float* d = xw + ch * 64 + i * 8;
        d[0]=a.x; d[1]=a.y; d[2]=a.z; d[3]=a.w;
        d[4]=b.x; d[5]=b.y; d[6]=b.z; d[7]=b.w;
    }
    const float* wb = qkw + (size_t)cls * 8192;
    for (int id = tid; id < 8192; id += 256)
        wsm[(id >> 6) * 65 + (id & 63)] = wb[id];
    const float* rb = relb + cls * 900;
    for (int id = tid; id < 900; id += 256) rsm[id] = rb[id];
    __syncthreads();

    const float* sS = qks + cls * 128;
    const float* sB = qkb + cls * 128;
    {
        int ocp = tid >> 2;
        int px0 = (tid & 3) * 16;
        u64 acc[2][8];
        #pragma unroll
        for (int r = 0; r < 2; r++)
            #pragma unroll
            for (int j = 0; j < 8; j++) acc[r][j] = 0ull;
        const float* w0r = wsm + (2 * ocp) * 65;
        const float* w1r = wsm + (2 * ocp + 1) * 65;
        #pragma unroll 4
        for (int c = 0; c < 64; c++) {
            u64 wa = bc2(w0r[c]);
            u64 wb2 = bc2(w1r[c]);
            const u64* xp = (const u64*)(xw + c * 64 + px0);
            #pragma unroll
            for (int j = 0; j < 8; j++) {
                u64 x2 = xp[j];
                fma2(acc[0][j], wa, x2);
                fma2(acc[1][j], wb2, x2);
            }
        }
        #pragma unroll
        for (int r = 0; r < 2; r++) {
            int oc = 2 * ocp + r;
            float s = sS[oc], b = sB[oc];
            #pragma unroll
            for (int j = 0; j < 8; j++) {
                float2 v = upk(acc[r][j]);
                qk[oc * 65 + px0 + 2 * j]     = fmaxf(v.x * s + b, 0.f);
                qk[oc * 65 + px0 + 2 * j + 1] = fmaxf(v.y * s + b, 0.f);
            }
        }
    }
    __syncthreads();

    float* gbase = g_qk + (size_t)(cls * NWIN + win) * 8192;
    for (int id = tid; id < 4096; id += 256) {
        int h = id >> 10, rem = id & 1023, px = rem >> 4, d = rem & 15;
        kl[id] = qk[(64 + h * 16 + d) * 65 + px];
    }
    for (int id = tid; id < 4096; id += 256)
        gbase[id] = qk[(id >> 6) * 65 + (id & 63)];
    if (tid < 64) {
        float s = 0.f;
        const float* r = qk + tid * 65;
        #pragma unroll 16
        for (int p = 0; p < 64; p++) s += r[p];
        qsum[tid] = s;
    }
    __syncthreads();

    {
        float4* gk4 = (float4*)(gbase + 4096);
        const float4* kl4 = (const float4*)kl;
        for (int id = tid; id < 1024; id += 256) gk4[id] = kl4[id];
    }

    if (tid < 64) {
        int kp = tid, ik = kp >> 3, jk = kp & 7;
        float dot = 0.f;
        #pragma unroll 16
        for (int ch = 0; ch < 64; ch++) dot += qsum[ch] * qk[(64 + ch) * 65 + kp];
        float rbv = 0.f;
        for (int q = 0; q < 64; q++) {
            int ridx = ((q >> 3) - ik + 7) * 15 + ((q & 7) - jk + 7);
            const float* r4 = rsm + ridx * 4;
            rbv += r4[0] + r4[1] + r4[2] + r4[3];
        }
        g_mask[(cls * NWIN + win) * 64 + kp] = dot * (0.25f / 256.f) + rbv * (1.f / 256.f);
    }
}

// ---------------------------------------------------------------------------
__global__ void k_good() {
    int i = blockIdx.x * 256 + threadIdx.x;
    float m[NCLS], mx = -1e30f;
    #pragma unroll
    for (int c = 0; c < NCLS; c++) {
        m[c] = g_mask[c * NWIN * 64 + i];
        mx = fmaxf(mx, m[c]);
    }
    #pragma unroll
    for (int c = 0; c < NCLS; c++)
        g_good[c * NWIN * 64 + i] = (m[c] == mx) ? 1.f : -1.f;
}

// ---------------------------------------------------------------------------
// K3: attention (loads q/k from g_qk), v conv, softmax, mask, attn@v,
//     residual + un-window.
// ---------------------------------------------------------------------------
__global__ __launch_bounds__(256)
void k_attn(const float* __restrict__ x, const float* __restrict__ relb,
            const float* __restrict__ wvw, const float* __restrict__ wvs,
            const float* __restrict__ wvb) {
    int cls = blockIdx.y, win = blockIdx.x;
    int wy = win >> 5, wx = win & 31;
    extern __shared__ float sm[];
    float* xw  = sm;             // 4096
    float* qsm = xw + 4096;      // 4160
    float* ksm = qsm + 4160;     // 4096
    float* vsm = ksm + 4096;     // 4096
    float* wsm = vsm + 4096;     // 4160
    float* rsm = wsm + 4160;     // 900
    float* gsm = rsm + 900;      // 64
    float* osm = gsm + 64;       // 4096
    int tid = threadIdx.x;
    const float* xb = x + ((size_t)cls * CN) * HWSZ;

    for (int id = tid; id < 512; id += 256) {
        int ch = id >> 3, i = id & 7;
        const float* p = xb + (size_t)ch * HWSZ + (wy * 8 + i) * HH + wx * 8;
        float4 a = *(const float4*)p;
        float4 b = *(const float4*)(p + 4);
        float* d = xw + ch * 64 + i * 8;
        d[0]=a.x; d[1]=a.y; d[2]=a.z; d[3]=a.w;
        d[4]=b.x; d[5]=b.y; d[6]=b.z; d[7]=b.w;
    }
    const float* gbase = g_qk + (size_t)(cls * NWIN + win) * 8192;
    for (int id = tid; id < 4096; id += 256)
        qsm[(id >> 6) * 65 + (id & 63)] = gbase[id];
    {
        const float4* gk4 = (const float4*)(gbase + 4096);
        float4* k4 = (float4*)ksm;
        for (int id = tid; id < 1024; id += 256) k4[id] = gk4[id];
    }
    const float* wvwb = wvw + (size_t)cls * 4096;
    for (int id = tid; id < 4096; id += 256)
        wsm[(id >> 6) * 65 + (id & 63)] = wvwb[id];
    const float* rb = relb + cls * 900;
    for (int id = tid; id < 900; id += 256) rsm[id] = rb[id];
    if (tid < 64) gsm[tid] = g_good[(cls * NWIN + win) * 64 + tid];
    __syncthreads();

    {
        int ocp = tid >> 3;
        int px0 = (tid & 7) * 8;
        u64 acc[2][4];
        #pragma unroll
        for (int r = 0; r < 2; r++)
            #pragma unroll
            for (int j = 0; j < 4; j++) acc[r][j] = 0ull;
        const float* w0r = wsm + (2 * ocp) * 65;
        const float* w1r = wsm + (2 * ocp + 1) * 65;
        #pragma unroll 4
        for (int c = 0; c < 64; c++) {
            u64 wa = bc2(w0r[c]);
            u64 wb2 = bc2(w1r[c]);
            const u64* xp = (const u64*)(xw + c * 64 + px0);
            #pragma unroll
            for (int j = 0; j < 4; j++) {
                u64 x2 = xp[j];
                fma2(acc[0][j], wa, x2);
                fma2(acc[1][j], wb2, x2);
            }
        }
        const float* vS = wvs + cls * 64;
        const float* vB = wvb + cls * 64;
        #pragma unroll
        for (int r = 0; r < 2; r++) {
            int oc = 2 * ocp + r;
            int h = oc >> 4, d = oc & 15;
            float s = vS[oc], b = vB[oc];
            #pragma unroll
            for (int j = 0; j < 4; j++) {
                float2 v = upk(acc[r][j]);
                vsm[h * 1024 + (px0 + 2 * j) * 16 + d]     = fmaxf(v.x * s + b, 0.f);
                vsm[h * 1024 + (px0 + 2 * j + 1) * 16 + d] = fmaxf(v.y * s + b, 0.f);
            }
        }
    }
    __syncthreads();

    int h = tid >> 6, qp = tid & 63;
    int iq = qp >> 3, jq = qp & 7;
    u64 q2[8];
    #pragma unroll
    for (int j = 0; j < 8; j++)
        q2[j] = pk2(qsm[(h * 16 + 2 * j) * 65 + qp], qsm[(h * 16 + 2 * j + 1) * 65 + qp]);

    float a[64];
    const u64* kb2 = (const u64*)(ksm + h * 1024);
    #pragma unroll
    for (int kp = 0; kp < 64; kp++) {
        const u64* kr = kb2 + kp * 8;
        u64 dacc = 0ull;
        #pragma unroll
        for (int j = 0; j < 8; j++) fma2(dacc, q2[j], kr[j]);
        float2 dv = upk(dacc);
        int ridx = (iq - (kp >> 3) + 7) * 15 + (jq - (kp & 7) + 7);
        a[kp] = (dv.x + dv.y) * 0.25f + rsm[ridx * 4 + h];
    }
    float mx = -1e30f;
    #pragma unroll
    for (int kp = 0; kp < 64; kp++) mx = fmaxf(mx, a[kp]);
    float ssum = 0.f;
    #pragma unroll
    for (int kp = 0; kp < 64; kp++) { a[kp] = __expf(a[kp] - mx); ssum += a[kp]; }
    float gq = gsm[qp] / ssum;

    u64 o2[8];
    #pragma unroll
    for (int j = 0; j < 8; j++) o2[j] = 0ull;
    const u64* vb3 = (const u64*)(vsm + h * 1024);
    #pragma unroll
    for (int kp = 0; kp < 64; kp++) {
        u64 w2 = bc2(a[kp] * gq * gsm[kp]);
        const u64* vr = vb3 + kp * 8;
        #pragma unroll
        for (int j = 0; j < 8; j++) fma2(o2[j], w2, vr[j]);
    }
    #pragma unroll
    for (int j = 0; j < 8; j++) {
        float2 ov = upk(o2[j]);
        int c0 = h * 16 + 2 * j;
        osm[c0 * 64 + qp]       = ov.x + xw[c0 * 64 + qp];
        osm[(c0 + 1) * 64 + qp] = ov.y + xw[(c0 + 1) * 64 + qp];
    }
    __syncthreads();

    float* ob = g_out1 + ((size_t)cls * CN) * HWSZ;
    for (int id = tid; id < 512; id += 256) {
        int ch = id >> 3, i = id & 7;
        const float* src = osm + ch * 64 + i * 8;
        float4 a4 = {src[0], src[1], src[2], src[3]};
        float4 b4 = {src[4], src[5], src[6], src[7]};
        float* p = ob + (size_t)ch * HWSZ + (wy * 8 + i) * HH + wx * 8;
        *(float4*)p = a4;
        *(float4*)(p + 4) = b4;
    }
}

// ---------------------------------------------------------------------------
// K4: sum of M conv3x3-BN-relu6. 8x4 tile, chunk=4 channels, cp.async
// double-buffered transposed weights, interleaved (px, px+4) f32x2 pairs.
// ---------------------------------------------------------------------------
template <int M, int OCC>
__global__ __launch_bounds__(256, OCC)
void k_conv3(int src_id, int dst_id,
             const float* __restrict__ s, const float* __restrict__ b, int m0) {
    int cls = blockIdx.z;
    int tx0 = blockIdx.x * 8, ty0 = blockIdx.y * 4;
    const float* src = (src_id == 0 ? g_out1 : (src_id == 1 ? g_x112 : g_x223))
                       + (size_t)cls * CN * HWSZ;
    float* dst = (dst_id == 1 ? g_x112 : (dst_id == 2 ? g_x223 : g_x33))
                 + (size_t)cls * CN * HWSZ;
    extern __shared__ float sm[];
    float* ism = sm;                 // 64*6*12 = 4608 (interleaved halo)
    float* wb0 = ism + 4608;         // M*2304
    float* wb1 = wb0 + M * 2304;     // M*2304
    unsigned smb = (unsigned)__cvta_generic_to_shared(sm);
    unsigned wbu[2] = { smb + 4608u * 4u, smb + (4608u + (unsigned)M * 2304u) * 4u };
    int tid = threadIdx.x;
    int oc = tid & 63, grp = tid >> 6;

    // interleaved halo: per (c,row) 12 slots, slot p -> col (p>>1) + 4*(p&1) - 1
    for (int id = tid; id < 4608; id += 256) {
        int c = id / 72, rem = id - c * 72;
        int r = rem / 12, p = rem - r * 12;
        int gy = ty0 + r - 1, gx = tx0 + (p >> 1) + 4 * (p & 1) - 1;
        float v = 0.f;
        if ((unsigned)gy < 256u && (unsigned)gx < 256u)
            v = src[(size_t)c * HWSZ + gy * HH + gx];
        ism[id] = v;
    }
    const float* wT = g_wT + (size_t)(cls * 6 + m0) * 576 * 64;

    // prologue: chunk 0 -> buffer 0
    for (int id = tid; id < M * 576; id += 256) {
        int mo = id / 576, i = id - mo * 576;
        cpasync16(wbu[0] + (unsigned)(mo * 2304 + i * 4) * 4u,
                  wT + mo * 36864 + i * 4);
    }
    cpcommit();

    u64 acc[M][4];
    #pragma unroll
    for (int m = 0; m < M; m++)
        #pragma unroll
        for (int j = 0; j < 4; j++) acc[m][j] = 0ull;

    for (int ci = 0; ci < 16; ci++) {
        cpwait0();
        __syncthreads();
        const float* cur = (ci & 1) ? wb1 : wb0;
        if (ci < 15) {
            unsigned dstb = wbu[(ci + 1) & 1];
            const float* srcb = wT + (ci + 1) * 2304;
            for (int id = tid; id < M * 576; id += 256) {
                int mo = id / 576, i = id - mo * 576;
                cpasync16(dstb + (unsigned)(mo * 2304 + i * 4) * 4u,
                          srcb + mo * 36864 + i * 4);
            }
        }
        cpcommit();
        #pragma unroll
        for (int lc = 0; lc < 4; lc++) {
            const float* ib = ism + (ci * 4 + lc) * 72 + grp * 12;
            #pragma unroll
            for (int ky = 0; ky < 3; ky++) {
                const u64* P = (const u64*)(ib + ky * 12);
                u64 p0 = P[0], p1 = P[1], p2 = P[2], p3 = P[3], p4 = P[4], p5 = P[5];
                #pragma unroll
                for (int m = 0; m < M; m++) {
                    const float* wp = cur + m * 2304 + (lc * 9 + ky * 3) * 64 + oc;
                    u64 w0 = bc2(wp[0]), w1 = bc2(wp[64]), w2 = bc2(wp[128]);
                    fma2(acc[m][0], w0, p0); fma2(acc[m][0], w1, p1); fma2(acc[m][0], w2, p2);
                    fma2(acc[m][1], w0, p1); fma2(acc[m][1], w1, p2); fma2(acc[m][1], w2, p3);
                    fma2(acc[m][2], w0, p2); fma2(acc[m][2], w1, p3); fma2(acc[m][2], w2, p4);
                    fma2(acc[m][3], w0, p3); fma2(acc[m][3], w1, p4); fma2(acc[m][3], w2, p5);
                }
            }
        }
    }

    float res[8];
    #pragma unroll
    for (int j = 0; j < 8; j++) res[j] = 0.f;
    #pragma unroll
    for (int m = 0; m < M; m++) {
        float sv = s[((size_t)cls * 6 + m0 + m) * 64 + oc];
        float bv = b[((size_t)cls * 6 + m0 + m) * 64 + oc];
        #pragma unroll
        for (int j = 0; j < 4; j++) {
            float2 v = upk(acc[m][j]);
            res[j]     += fminf(fmaxf(v.x * sv + bv, 0.f), 6.f);
            res[j + 4] += fminf(fmaxf(v.y * sv + bv, 0.f), 6.f);
        }
    }
    // stage to osm (reuse wb0; threads finished reading wb0 chunks already)
    float* osm = wb0;   // need 64*36 = 2304 <= M*2304 ✓
    {
        float4 a4 = {res[0], res[1], res[2], res[3]};
        float4 b4 = {res[4], res[5], res[6], res[7]};
        *(float4*)(osm + oc * 36 + grp * 8)     = a4;
        *(float4*)(osm + oc * 36 + grp * 8 + 4) = b4;
    }
    __syncthreads();
    for (int id = tid; id < 512; id += 256) {
        int oc2 = id >> 3, rq = id & 7, r = rq >> 1, q = rq & 1;
        float4 v = *(const float4*)(osm + oc2 * 36 + r * 8 + q * 4);
        *(float4*)(dst + (size_t)oc2 * HWSZ + (ty0 + r) * HH + tx0 + q * 4) = v;
    }
}

// ---------------------------------------------------------------------------
// K5: concat 1x1-BN over [x112, x223, x33] + residual + relu, src-by-src
// staged (small smem -> 4 CTAs/SM), direct global writes.
// ---------------------------------------------------------------------------
__global__ __launch_bounds__(256, 4)
void k_out(const float* __restrict__ catw, const float* __restrict__ cats,
           const float* __restrict__ catb, float* __restrict__ out) {
    int cls = blockIdx.z;
    int tx0 = blockIdx.x * 16, ty0 = blockIdx.y * 4;
    extern __shared__ float sm[];
    float* xsm = sm;           // 4096
    float* cwsm = xsm + 4096;  // 64*65 = 4160
    int tid = threadIdx.x;
    int ocp = tid >> 3, seg = tid & 7;
    int px0 = seg * 8;

    u64 acc[2][4];
    #pragma unroll
    for (int r = 0; r < 2; r++)
        #pragma unroll
        for (int j = 0; j < 4; j++) acc[r][j] = 0ull;

    const float* srcs[3] = {
        g_x112 + (size_t)cls * CN * HWSZ,
        g_x223 + (size_t)cls * CN * HWSZ,
        g_x33  + (size_t)cls * CN * HWSZ
    };
    const float* cwb = catw + (size_t)cls * 64 * 192;

    for (int sidx = 0; sidx < 3; sidx++) {
        __syncthreads();
        const float* srcp = srcs[sidx];
        for (int id = tid; id < 4096; id += 256) {
            int c = id >> 6, px = id & 63, r = px >> 4, col = px & 15;
            xsm[id] = srcp[(size_t)c * HWSZ + (ty0 + r) * HH + tx0 + col];
        }
        for (int id = tid; id < 4096; id += 256) {
            int o2 = id >> 6, c = id & 63;
            cwsm[o2 * 65 + c] = cwb[o2 * 192 + sidx * 64 + c];
        }
        __syncthreads();
        const float* w0r = cwsm + (2 * ocp) * 65;
        const float* w1r = cwsm + (2 * ocp + 1) * 65;
        #pragma unroll 4
        for (int c = 0; c < 64; c++) {
            u64 wa = bc2(w0r[c]);
            u64 wb2 = bc2(w1r[c]);
            const u64* xp = (const u64*)(xsm + c * 64 + px0);
            #pragma unroll
            for (int j = 0; j < 4; j++) {
                u64 v = xp[j];
                fma2(acc[0][j], wa, v);
                fma2(acc[1][j], wb2, v);
            }
        }
    }

    int r = seg >> 1, col0 = (seg & 1) * 8;
    const float* o1 = g_out1 + (size_t)cls * CN * HWSZ;
    float* ob = out + ((size_t)cls * CN) * HWSZ;
    #pragma unroll
    for (int rr = 0; rr < 2; rr++) {
        int oc = 2 * ocp + rr;
        float csv = cats[cls * 64 + oc], cbv = catb[cls * 64 + oc];
        float v[8];
        #pragma unroll
        for (int j = 0; j < 4; j++) {
            float2 t = upk(acc[rr][j]);
            v[2 * j] = t.x; v[2 * j + 1] = t.y;
        }
        const float* rp = o1 + (size_t)oc * HWSZ + (ty0 + r) * HH + tx0 + col0;
        float4 ra = *(const float4*)rp;
        float4 rb = *(const float4*)(rp + 4);
        float4 oa, obv;
        oa.x = fmaxf(v[0] * csv + cbv + ra.x, 0.f);
        oa.y = fmaxf(v[1] * csv + cbv + ra.y, 0.f);
        oa.z = fmaxf(v[2] * csv + cbv + ra.z, 0.f);
        oa.w = fmaxf(v[3] * csv + cbv + ra.w, 0.f);
        obv.x = fmaxf(v[4] * csv + cbv + rb.x, 0.f);
        obv.y = fmaxf(v[5] * csv + cbv + rb.y, 0.f);
        obv.z = fmaxf(v[6] * csv + cbv + rb.z, 0.f);
        obv.w = fmaxf(v[7] * csv + cbv + rb.w, 0.f);
        float* op = ob + (size_t)oc * HWSZ + (ty0 + r) * HH + tx0 + col0;
        *(float4*)op = oa;
        *(float4*)(op + 4) = obv;
    }
}

// ---------------------------------------------------------------------------
extern "C" void kernel_launch(void* const* d_in, const int* in_sizes, int n_in,
                              void* d_out, int out_size) {
    const float* x    = (const float*)d_in[0];
    const float* qkw  = (const float*)d_in[1];
    const float* qks  = (const float*)d_in[2];
    const float* qkb  = (const float*)d_in[3];
    const float* relb = (const float*)d_in[4];
    const float* wvw  = (const float*)d_in[5];
    const float* wvs  = (const float*)d_in[6];
    const float* wvb  = (const float*)d_in[7];
    const float* mmsw = (const float*)d_in[8];
    const float* mmss = (const float*)d_in[9];
    const float* mmsb = (const float*)d_in[10];
    const float* catw = (const float*)d_in[11];
    const float* cats = (const float*)d_in[12];
    const float* catb = (const float*)d_in[13];
    float* out = (float*)d_out;

    const int SM_MASK = (4096 + 8320 + 8320 + 4096 + 64 + 900) * 4;
    const int SM_ATTN = (4096 + 4160 + 4096 + 4096 + 4160 + 900 + 64 + 4096) * 4;
    const int SM_C3   = (4608 + 2 * 3 * 2304) * 4;   // 73728
    const int SM_C2   = (4608 + 2 * 2 * 2304) * 4;   // 55296
    const int SM_C1   = (4608 + 2 * 1 * 2304) * 4;   // 36864
    const int SM_OUT  = (4096 + 4160) * 4;           // 33024

    cudaFuncSetAttribute(k_mask, cudaFuncAttributeMaxDynamicSharedMemorySize, SM_MASK);
    cudaFuncSetAttribute(k_attn, cudaFuncAttributeMaxDynamicSharedMemorySize, SM_ATTN);
    cudaFuncSetAttribute((const void*)k_conv3<3,3>, cudaFuncAttributeMaxDynamicSharedMemorySize, SM_C3);
    cudaFuncSetAttribute((const void*)k_conv3<2,4>, cudaFuncAttributeMaxDynamicSharedMemorySize, SM_C2);
    cudaFuncSetAttribute((const void*)k_conv3<1,4>, cudaFuncAttributeMaxDynamicSharedMemorySize, SM_C1);
    cudaFuncSetAttribute(k_out,  cudaFuncAttributeMaxDynamicSharedMemorySize, SM_OUT);

    k_prep<<<(NCLS * 6 * 64 * 576 + 255) / 256, 256>>>(mmsw);
    k_mask<<<dim3(NWIN, NCLS), 256, SM_MASK>>>(x, qkw, qks, qkb, relb);
    k_good<<<256, 256>>>();
    k_attn<<<dim3(NWIN, NCLS), 256, SM_ATTN>>>(x, relb, wvw, wvs, wvb);
    dim3 cg(32, 64, NCLS);
    k_conv3<3,3><<<cg, 256, SM_C3>>>(0, 1, mmss, mmsb, 0);
    k_conv3<2,4><<<cg, 256, SM_C2>>>(1, 2, mmss, mmsb, 3);
    k_conv3<1,4><<<cg, 256, SM_C1>>>(2, 3, mmss, mmsb, 5);
    dim3 og(16, 64, NCLS);
    k_out<<<og, 256, SM_OUT>>>(catw, cats, catb, out);
}